// round 16
// baseline (speedup 1.0000x reference)
#include <cuda_runtime.h>
#include <cuda_bf16.h>
#include <cuda_fp16.h>
#include <math.h>
#include <stdint.h>

#define MAXN 100000
#define ROWS_PAD 100096   // MAXN rounded up to 128
#define MAXM 1600000
#define DIMD 128
#define TOPK 16
#define INV_SQRT_D 0.08838834764831845f
#define BST 80   // bf16 row stride of A/B SMEM tiles (160B: conflict-free LDS.64)

// ---------------- device scratch (no allocations allowed) ----------------
__device__ float  g_Qv[(size_t)MAXN * DIMD];   // Qv rows, fp32
__device__ __half g_Kh[(size_t)MAXN * DIMD];   // Ku rows, fp16
__device__ __half g_Xh[(size_t)MAXN * DIMD];   // X rows, fp16 (attn gather copy)
__device__ float  g_H[(size_t)MAXN * DIMD];    // weighted neighbor sum per dst
// X pre-split into bf16 hi/lo, SMEM-image layout: [hl][ch][row*BST + pos]
__device__ __nv_bfloat16 g_Xsplit[2][2][(size_t)ROWS_PAD * BST];
// Weight bf16 hi/lo images: [w][hl][kchunk][c*BST + pos]; 0=Wself 1=Wmsg 2=Wq 3=Wk
__device__ __nv_bfloat16 g_Wsplit[4][2][2][128 * BST];
__device__ int   g_deg[MAXN];
__device__ int   g_off[MAXN];
__device__ int   g_cur[MAXN];
__device__ int2  g_edge[MAXM + 8];   // {src, bitcast(dec)} packed
__device__ int   g_is64;
__device__ int   g_total;

__device__ __forceinline__ int get_idx(const void* p, int is64, long long i) {
    return is64 ? (int)((const long long*)p)[i] : ((const int*)p)[i];
}

// k-interleave permutation for pairs (see fragment layout of mma m16n8k16)
__device__ __forceinline__ int pair_pos(int j) {   // j = k & 15, even
    return ((j & 7) >> 1) * 4 + ((j >> 3) & 1) * 2;
}

// ---------------- K0: prep (deg zero, weight+X images, Xh, idx dtype) -------
__global__ void prep_kernel(const float* __restrict__ X, const void* eidx,
                            const float* __restrict__ Wself, const float* __restrict__ Wmsg,
                            const float* __restrict__ Wq, const float* __restrict__ Wk,
                            int n) {
    int idx = blockIdx.x * blockDim.x + threadIdx.x;
    int nth = gridDim.x * blockDim.x;
    if (idx == 0) g_total = 0;
    if (idx < n) g_deg[idx] = 0;
    if (idx < 4 * 128 * 128) {
        int w = idx >> 14;
        int e = idx & 16383;
        int c = e >> 7;      // output col index (mma n)
        int k = e & 127;     // K index
        const float* W = (w == 0) ? Wself : (w == 1) ? Wmsg : (w == 2) ? Wq : Wk;
        float v = W[c * DIMD + k];
        __nv_bfloat16 hi = __float2bfloat16(v);
        __nv_bfloat16 lo = __float2bfloat16(v - __bfloat162float(hi));
        int ch = k >> 6, kk = k & 63;
        int g = kk >> 4, j = kk & 15;
        int pos = ((j & 7) >> 1) * 4 + ((j >> 3) & 1) * 2 + (j & 1);
        int off = c * BST + g * 16 + pos;
        g_Wsplit[w][0][ch][off] = hi;
        g_Wsplit[w][1][ch][off] = lo;
    }
    // X -> fp16 gather copy + bf16 hi/lo SMEM-image copies (grid-stride pairs)
    long long tot = (long long)ROWS_PAD * 64;   // pairs over full padded rows
    for (long long f = idx; f < tot; f += nth) {
        int row = (int)(f >> 6);
        int pk = (int)(f & 63);          // pair index: k = 2*pk
        int k2 = pk * 2;
        int ch = k2 >> 6, kk = k2 & 63;
        int g = kk >> 4, j = kk & 15;
        size_t pos = (size_t)row * BST + g * 16 + pair_pos(j);
        float2 v = make_float2(0.f, 0.f);
        if (row < n) v = ((const float2*)X)[(size_t)row * 64 + pk];
        __nv_bfloat16 h0 = __float2bfloat16(v.x);
        __nv_bfloat16 h1 = __float2bfloat16(v.y);
        __nv_bfloat16 l0 = __float2bfloat16(v.x - __bfloat162float(h0));
        __nv_bfloat16 l1 = __float2bfloat16(v.y - __bfloat162float(h1));
        *(__nv_bfloat162*)&g_Xsplit[0][ch][pos] = __nv_bfloat162(h0, h1);
        *(__nv_bfloat162*)&g_Xsplit[1][ch][pos] = __nv_bfloat162(l0, l1);
        if (row < n) ((__half2*)g_Xh)[(size_t)row * 64 + pk] = __floats2half2_rn(v.x, v.y);
    }
    if (blockIdx.x == 0) {
        __shared__ int flag;
        if (threadIdx.x == 0) flag = 0;
        __syncthreads();
        const unsigned int* w = (const unsigned int*)eidx;
        if (threadIdx.x < 256 && w[2 * threadIdx.x + 1] != 0u) atomicOr(&flag, 1);
        __syncthreads();
        if (threadIdx.x == 0) g_is64 = flag ? 0 : 1;
    }
}

// ---------------- K2: histogram of dst ----------------
__global__ void hist_kernel(const void* eidx, int m) {
    int e = blockIdx.x * blockDim.x + threadIdx.x;
    if (e >= m) return;
    int is64 = g_is64;
    int d = get_idx(eidx, is64, (long long)m + e);
    atomicAdd(&g_deg[d], 1);
}

// ---------------- K3: slab reservation ----------------
__global__ void offsets_kernel(int n) {
    int d = blockIdx.x * blockDim.x + threadIdx.x;
    if (d >= n) return;
    int deg = g_deg[d];
    int off = deg ? atomicAdd(&g_total, deg) : 0;
    g_off[d] = off;
    g_cur[d] = off;
}

// ---------------- K4: scatter edges into per-dst slabs ----------------
__global__ void scatter_kernel(const void* eidx, const float* __restrict__ edt, int m) {
    int e = blockIdx.x * blockDim.x + threadIdx.x;
    if (e >= m) return;
    int is64 = g_is64;
    int s = get_idx(eidx, is64, e);
    int d = get_idx(eidx, is64, (long long)m + e);
    int pos = atomicAdd(&g_cur[d], 1);
    g_edge[pos] = make_int2(s, __float_as_int(expf(-edt[e])));
}

// ---------------- K5: per-dst score + top-16 + softmax + gather --------------
// Both gathers fp16 (Kh, Xh): 256B/row; fp32 accumulation throughout.
__global__ void __launch_bounds__(256) attn_kernel(int n) {
    int warp = (blockIdx.x * blockDim.x + threadIdx.x) >> 5;
    int lane = threadIdx.x & 31;
    if (warp >= n) return;
    int d = warp;
    int deg = g_deg[d];
    if (deg == 0) {
        ((float4*)g_H)[(size_t)d * 32 + lane] = make_float4(0.f, 0.f, 0.f, 0.f);
        return;
    }
    int off = g_off[d];
    const float4* Qv4 = (const float4*)g_Qv;
    float4 q = Qv4[(size_t)d * 32 + lane];   // Qv[d], dims [4*lane, 4*lane+4)

    float s0 = -INFINITY, s1 = -INFINITY, s2 = -INFINITY, s3 = -INFINITY;
    int r0 = -1, r1 = -1, r2 = -1, r3 = -1;

    int jmax = deg < 128 ? deg : 128;
    for (int j = 0; j < jmax; j++) {
        int2 ed = g_edge[off + j];
        int src = ed.x;
        uint2 kv = ((const uint2*)(g_Kh + (size_t)src * DIMD))[lane];  // 4 fp16
        float2 f0 = __half22float2(*(__half2*)&kv.x);
        float2 f1 = __half22float2(*(__half2*)&kv.y);
        float p = q.x * f0.x + q.y * f0.y + q.z * f1.x + q.w * f1.y;
        #pragma unroll
        for (int o = 16; o; o >>= 1) p += __shfl_xor_sync(0xffffffffu, p, o);
        float sc = p * INV_SQRT_D * __int_as_float(ed.y);
        if ((j & 31) == lane) {
            int sl = j >> 5;
            if (sl == 0) { s0 = sc; r0 = src; }
            else if (sl == 1) { s1 = sc; r1 = src; }
            else if (sl == 2) { s2 = sc; r2 = src; }
            else             { s3 = sc; r3 = src; }
        }
    }
    for (int j = 128; j < deg; j++) {
        int2 ed = g_edge[off + j];
        int src = ed.x;
        uint2 kv = ((const uint2*)(g_Kh + (size_t)src * DIMD))[lane];
        float2 f0 = __half22float2(*(__half2*)&kv.x);
        float2 f1 = __half22float2(*(__half2*)&kv.y);
        float p = q.x * f0.x + q.y * f0.y + q.z * f1.x + q.w * f1.y;
        #pragma unroll
        for (int o = 16; o; o >>= 1) p += __shfl_xor_sync(0xffffffffu, p, o);
        float sc = p * INV_SQRT_D * __int_as_float(ed.y);
        float mv = s0; int msl = 0;
        if (s1 < mv) { mv = s1; msl = 1; }
        if (s2 < mv) { mv = s2; msl = 2; }
        if (s3 < mv) { mv = s3; msl = 3; }
        float bv = mv; int bl = lane;
        #pragma unroll
        for (int o = 16; o; o >>= 1) {
            float ov = __shfl_xor_sync(0xffffffffu, bv, o);
            int   ol = __shfl_xor_sync(0xffffffffu, bl, o);
            if (ov < bv || (ov == bv && ol < bl)) { bv = ov; bl = ol; }
        }
        if (sc > bv && lane == bl) {
            if (msl == 0) { s0 = sc; r0 = src; }
            else if (msl == 1) { s1 = sc; r1 = src; }
            else if (msl == 2) { s2 = sc; r2 = src; }
            else              { s3 = sc; r3 = src; }
        }
    }

    int K = deg < TOPK ? deg : TOPK;
    float sel_v; int sel_src;
    if (deg <= TOPK) {
        sel_v = s0; sel_src = r0;
    } else {
        sel_v = -INFINITY; sel_src = -1;
        for (int it = 0; it < TOPK; it++) {
            float v = s0; int sl = 0;
            if (s1 > v) { v = s1; sl = 1; }
            if (s2 > v) { v = s2; sl = 2; }
            if (s3 > v) { v = s3; sl = 3; }
            float bv = v; int bl = lane;
            #pragma unroll
            for (int o = 16; o; o >>= 1) {
                float ov = __shfl_xor_sync(0xffffffffu, bv, o);
                int   ol = __shfl_xor_sync(0xffffffffu, bl, o);
                if (ov > bv || (ov == bv && ol < bl)) { bv = ov; bl = ol; }
            }
            int bslot = __shfl_sync(0xffffffffu, sl, bl);
            int csrc = (bslot == 0) ? r0 : (bslot == 1) ? r1 : (bslot == 2) ? r2 : r3;
            int bsrc = __shfl_sync(0xffffffffu, csrc, bl);
            if (lane == bl) {
                if (bslot == 0) s0 = -INFINITY;
                else if (bslot == 1) s1 = -INFINITY;
                else if (bslot == 2) s2 = -INFINITY;
                else                 s3 = -INFINITY;
            }
            if (lane == it) { sel_v = bv; sel_src = bsrc; }
        }
    }

    float mred = (sel_src >= 0) ? sel_v : -INFINITY;
    #pragma unroll
    for (int o = 16; o; o >>= 1) mred = fmaxf(mred, __shfl_xor_sync(0xffffffffu, mred, o));
    float w = (sel_src >= 0) ? expf(sel_v - mred) : 0.f;
    float wsum = w;
    #pragma unroll
    for (int o = 16; o; o >>= 1) wsum += __shfl_xor_sync(0xffffffffu, wsum, o);
    float alpha = w / wsum;

    float4 acc = make_float4(0.f, 0.f, 0.f, 0.f);
    for (int k2 = 0; k2 < K; k2++) {
        float a = __shfl_sync(0xffffffffu, alpha, k2);
        int  sr = __shfl_sync(0xffffffffu, sel_src, k2);
        uint2 xv = ((const uint2*)(g_Xh + (size_t)sr * DIMD))[lane];
        float2 x0 = __half22float2(*(__half2*)&xv.x);
        float2 x1 = __half22float2(*(__half2*)&xv.y);
        acc.x += a * x0.x; acc.y += a * x0.y; acc.z += a * x1.x; acc.w += a * x1.y;
    }
    ((float4*)g_H)[(size_t)d * 32 + lane] = acc;
}

// ---------------- bf16 mma.sync helper ----------------
__device__ __forceinline__ void mma_bf16(float* c, const uint32_t* a, const uint32_t* b) {
    asm volatile(
        "mma.sync.aligned.m16n8k16.row.col.f32.bf16.bf16.f32 "
        "{%0,%1,%2,%3}, {%4,%5,%6,%7}, {%8,%9}, {%0,%1,%2,%3};"
        : "+f"(c[0]), "+f"(c[1]), "+f"(c[2]), "+f"(c[3])
        : "r"(a[0]), "r"(a[1]), "r"(a[2]), "r"(a[3]), "r"(b[0]), "r"(b[1]));
}

// ---------------- K1/K6: bf16x3 split-precision mma.sync GEMM ---------------
// X chunks: A-fill = vector copy from pre-split g_Xsplit. H chunks: inline cvt.
// mode 0: bx=0 -> Qv = X*Wq^T (fp32); bx=1 -> Kh = X*Wk^T (fp16)   2 chunks
// mode 1: out = relu(X*Wself^T + H*Wmsg^T)                          4 chunks
__global__ void __launch_bounds__(256, 2) mma_gemm(int mode, float* __restrict__ Cext,
                                                   int n) {
    extern __shared__ __nv_bfloat16 sm[];
    __nv_bfloat16* Ahi = sm;
    __nv_bfloat16* Alo = sm + 128 * BST;
    __nv_bfloat16* Bhi = sm + 2 * 128 * BST;
    __nv_bfloat16* Blo = sm + 3 * 128 * BST;

    int tid = threadIdx.x;
    int lane = tid & 31;
    int warp = tid >> 5;
    int wm = warp >> 1;
    int wn = warp & 1;
    int gr = lane >> 2;
    int gc = lane & 3;
    int rowBase = blockIdx.y * 128;
    int nchunks = (mode == 0) ? 2 : 4;

    float acc[2][8][4];
    #pragma unroll
    for (int mi = 0; mi < 2; mi++)
        #pragma unroll
        for (int ni = 0; ni < 8; ni++)
            #pragma unroll
            for (int q = 0; q < 4; q++) acc[mi][ni][q] = 0.f;

    for (int ch = 0; ch < nchunks; ch++) {
        int xch = (ch < 2) ? ch : ch - 2;
        int wsel = (mode == 0) ? (2 + blockIdx.x) : (ch < 2 ? 0 : 1);
        bool fromX = (mode == 0) || (ch < 2);

        if (fromX) {
            // ---- A-fill: straight 16B copies of pre-split X image ----
            const uint4* shx = (const uint4*)&g_Xsplit[0][xch][(size_t)rowBase * BST];
            const uint4* slx = (const uint4*)&g_Xsplit[1][xch][(size_t)rowBase * BST];
            uint4* dh = (uint4*)Ahi;
            uint4* dl = (uint4*)Alo;
            #pragma unroll
            for (int p = 0; p < 5; p++) {   // 1280 uint4 per buffer
                int f = tid + p * 256;
                dh[f] = shx[f];
                dl[f] = slx[f];
            }
        } else {
            // ---- A-fill: convert H fp32 -> bf16 hi/lo ----
            #pragma unroll
            for (int p = 0; p < 16; p++) {
                int f = tid + p * 256;
                int row = f >> 5;
                int kk = (f & 31) * 2;
                int g = kk >> 4, j = kk & 15;
                int pos = row * BST + g * 16 + pair_pos(j);
                int grow = rowBase + row;
                float2 v = make_float2(0.f, 0.f);
                if (grow < n) v = *(const float2*)&g_H[(size_t)grow * DIMD + xch * 64 + kk];
                __nv_bfloat16 h0 = __float2bfloat16(v.x);
                __nv_bfloat16 h1 = __float2bfloat16(v.y);
                __nv_bfloat16 l0 = __float2bfloat16(v.x - __bfloat162float(h0));
                __nv_bfloat16 l1 = __float2bfloat16(v.y - __bfloat162float(h1));
                *(__nv_bfloat162*)&Ahi[pos] = __nv_bfloat162(h0, h1);
                *(__nv_bfloat162*)&Alo[pos] = __nv_bfloat162(l0, l1);
            }
        }
        {
            const uint4* sh = (const uint4*)&g_Wsplit[wsel][0][xch][0];
            const uint4* sl = (const uint4*)&g_Wsplit[wsel][1][xch][0];
            uint4* dh = (uint4*)Bhi;
            uint4* dl = (uint4*)Blo;
            #pragma unroll
            for (int p = 0; p < 5; p++) {
                int f = tid + p * 256;
                dh[f] = sh[f];
                dl[f] = sl[f];
            }
        }
        __syncthreads();

        #pragma unroll
        for (int g = 0; g < 4; g++) {
            uint32_t ahi[2][4], alo[2][4];
            #pragma unroll
            for (int mi = 0; mi < 2; mi++) {
                int r0 = wm * 32 + mi * 16 + gr;
                uint2 h0 = *(const uint2*)&Ahi[r0 * BST + g * 16 + gc * 4];
                uint2 h1 = *(const uint2*)&Ahi[(r0 + 8) * BST + g * 16 + gc * 4];
                ahi[mi][0] = h0.x; ahi[mi][2] = h0.y;
                ahi[mi][1] = h1.x; ahi[mi][3] = h1.y;
                uint2 l0 = *(const uint2*)&Alo[r0 * BST + g * 16 + gc * 4];
                uint2 l1 = *(const uint2*)&Alo[(r0 + 8) * BST + g * 16 + gc * 4];
                alo[mi][0] = l0.x; alo[mi][2] = l0.y;
                alo[mi][1] = l1.x; alo[mi][3] = l1.y;
            }
            #pragma unroll
            for (int ni = 0; ni < 8; ni++) {
                int nr = wn * 64 + ni * 8 + gr;
                uint2 bh = *(const uint2*)&Bhi[nr * BST + g * 16 + gc * 4];
                uint2 bl = *(const uint2*)&Blo[nr * BST + g * 16 + gc * 4];
                uint32_t bhv[2] = { bh.x, bh.y };
                uint32_t blv[2] = { bl.x, bl.y };
                mma_bf16(acc[0][ni], ahi[0], bhv);
                mma_bf16(acc[1][ni], ahi[1], bhv);
                mma_bf16(acc[0][ni], ahi[0], blv);
                mma_bf16(acc[1][ni], ahi[1], blv);
                mma_bf16(acc[0][ni], alo[0], bhv);
                mma_bf16(acc[1][ni], alo[1], bhv);
            }
        }
        __syncthreads();
    }

    int relu = (mode == 1);
    bool to_half = (mode == 0) && (blockIdx.x == 1);   // Kh output
    float* C = (mode == 0) ? g_Qv : Cext;
    #pragma unroll
    for (int mi = 0; mi < 2; mi++) {
        #pragma unroll
        for (int ni = 0; ni < 8; ni++) {
            int gcol = wn * 64 + ni * 8 + 2 * gc;
            int grow0 = rowBase + wm * 32 + mi * 16 + gr;
            float v0 = acc[mi][ni][0], v1 = acc[mi][ni][1];
            float v2 = acc[mi][ni][2], v3 = acc[mi][ni][3];
            if (relu) {
                v0 = fmaxf(v0, 0.f); v1 = fmaxf(v1, 0.f);
                v2 = fmaxf(v2, 0.f); v3 = fmaxf(v3, 0.f);
            }
            if (to_half) {
                if (grow0 < n)
                    *(__half2*)&g_Kh[(size_t)grow0 * DIMD + gcol] = __floats2half2_rn(v0, v1);
                if (grow0 + 8 < n)
                    *(__half2*)&g_Kh[(size_t)(grow0 + 8) * DIMD + gcol] = __floats2half2_rn(v2, v3);
            } else {
                if (grow0 < n)     *(float2*)&C[(size_t)grow0 * DIMD + gcol]       = make_float2(v0, v1);
                if (grow0 + 8 < n) *(float2*)&C[(size_t)(grow0 + 8) * DIMD + gcol] = make_float2(v2, v3);
            }
        }
    }
}

#define GEMM_SMEM (4 * 128 * BST * 2)

// ---------------- entry (serial chain — proven fastest ordering) ------------
extern "C" void kernel_launch(void* const* d_in, const int* in_sizes, int n_in,
                              void* d_out, int out_size) {
    const float* X     = (const float*)d_in[0];
    const void*  eidx  = d_in[1];
    const float* edt   = (const float*)d_in[2];
    const float* Wself = (const float*)d_in[3];
    const float* Wmsg  = (const float*)d_in[4];
    const float* Wq    = (const float*)d_in[5];
    const float* Wk    = (const float*)d_in[6];
    float* out = (float*)d_out;

    int n = in_sizes[0] / DIMD;
    int m = in_sizes[2];
    int rowTiles = (n + 127) / 128;

    cudaFuncSetAttribute(mma_gemm, cudaFuncAttributeMaxDynamicSharedMemorySize, GEMM_SMEM);

    prep_kernel<<<(n + 255) / 256, 256>>>(X, eidx, Wself, Wmsg, Wq, Wk, n);
    mma_gemm<<<dim3(2, rowTiles), 256, GEMM_SMEM>>>(0, nullptr, n);
    hist_kernel<<<(m + 255) / 256, 256>>>(eidx, m);
    offsets_kernel<<<(n + 255) / 256, 256>>>(n);
    scatter_kernel<<<(m + 255) / 256, 256>>>(eidx, edt, m);
    attn_kernel<<<(n + 7) / 8, 256>>>(n);
    mma_gemm<<<dim3(1, rowTiles), 256, GEMM_SMEM>>>(1, out, n);
}

// round 17
// speedup vs baseline: 1.0338x; 1.0338x over previous
#include <cuda_runtime.h>
#include <cuda_bf16.h>
#include <cuda_fp16.h>
#include <math.h>
#include <stdint.h>

#define MAXN 100000
#define MAXM 1600000
#define DIMD 128
#define TOPK 16
#define INV_SQRT_D 0.08838834764831845f
#define BST 80   // bf16 row stride of A/B SMEM tiles (160B: conflict-free LDS.64)

// ---------------- device scratch (no allocations allowed) ----------------
__device__ float  g_Qv[(size_t)MAXN * DIMD];   // Qv rows, fp32
__device__ __half g_Kh[(size_t)MAXN * DIMD];   // Ku rows, fp16
__device__ __half g_Xh[(size_t)MAXN * DIMD];   // X rows, fp16 (attn gather copy)
__device__ float  g_H[(size_t)MAXN * DIMD];    // weighted neighbor sum per dst
// Weight bf16 hi/lo images: [w][hl][kchunk][c*BST + pos]; 0=Wself 1=Wmsg 2=Wq 3=Wk
__device__ __nv_bfloat16 g_Wsplit[4][2][2][128 * BST];
__device__ int   g_deg[MAXN];
__device__ int   g_off[MAXN];
__device__ int   g_cur[MAXN];
__device__ int2  g_edge[MAXM + 8];   // {src, bitcast(dec)} packed
__device__ int   g_is64;
__device__ int   g_total;

__device__ __forceinline__ int get_idx(const void* p, int is64, long long i) {
    return is64 ? (int)((const long long*)p)[i] : ((const int*)p)[i];
}

// k-interleave permutation for pairs (see fragment layout of mma m16n8k16)
__device__ __forceinline__ int pair_pos(int j) {   // j = k & 15, even
    return ((j & 7) >> 1) * 4 + ((j >> 3) & 1) * 2;
}

// ---------------- K0: prep (deg zero, weight images, X->fp16, idx dtype) ----
__global__ void prep_kernel(const float* __restrict__ X, const void* eidx,
                            const float* __restrict__ Wself, const float* __restrict__ Wmsg,
                            const float* __restrict__ Wq, const float* __restrict__ Wk,
                            int n) {
    int idx = blockIdx.x * blockDim.x + threadIdx.x;
    int nth = gridDim.x * blockDim.x;
    if (idx == 0) g_total = 0;
    if (idx < n) g_deg[idx] = 0;
    if (idx < 4 * 128 * 128) {
        int w = idx >> 14;
        int e = idx & 16383;
        int c = e >> 7;      // output col index (mma n)
        int k = e & 127;     // K index
        const float* W = (w == 0) ? Wself : (w == 1) ? Wmsg : (w == 2) ? Wq : Wk;
        float v = W[c * DIMD + k];
        __nv_bfloat16 hi = __float2bfloat16(v);
        __nv_bfloat16 lo = __float2bfloat16(v - __bfloat162float(hi));
        int ch = k >> 6, kk = k & 63;
        int g = kk >> 4, j = kk & 15;
        int pos = ((j & 7) >> 1) * 4 + ((j >> 3) & 1) * 2 + (j & 1);
        int off = c * BST + g * 16 + pos;
        g_Wsplit[w][0][ch][off] = hi;
        g_Wsplit[w][1][ch][off] = lo;
    }
    // X -> fp16 gather copy (coalesced grid-stride over float2 pairs)
    long long tot = (long long)n * (DIMD / 2);
    for (long long f = idx; f < tot; f += nth) {
        float2 v = ((const float2*)X)[f];
        ((__half2*)g_Xh)[f] = __floats2half2_rn(v.x, v.y);
    }
    if (blockIdx.x == 0) {
        __shared__ int flag;
        if (threadIdx.x == 0) flag = 0;
        __syncthreads();
        const unsigned int* w = (const unsigned int*)eidx;
        if (threadIdx.x < 256 && w[2 * threadIdx.x + 1] != 0u) atomicOr(&flag, 1);
        __syncthreads();
        if (threadIdx.x == 0) g_is64 = flag ? 0 : 1;
    }
}

// ---------------- K2: histogram of dst ----------------
__global__ void hist_kernel(const void* eidx, int m) {
    int e = blockIdx.x * blockDim.x + threadIdx.x;
    if (e >= m) return;
    int is64 = g_is64;
    int d = get_idx(eidx, is64, (long long)m + e);
    atomicAdd(&g_deg[d], 1);
}

// ---------------- K3: slab reservation ----------------
__global__ void offsets_kernel(int n) {
    int d = blockIdx.x * blockDim.x + threadIdx.x;
    if (d >= n) return;
    int deg = g_deg[d];
    int off = deg ? atomicAdd(&g_total, deg) : 0;
    g_off[d] = off;
    g_cur[d] = off;
}

// ---------------- K4: scatter edges into per-dst slabs (packed int2) --------
__global__ void scatter_kernel(const void* eidx, const float* __restrict__ edt, int m) {
    int e = blockIdx.x * blockDim.x + threadIdx.x;
    if (e >= m) return;
    int is64 = g_is64;
    int s = get_idx(eidx, is64, e);
    int d = get_idx(eidx, is64, (long long)m + e);
    int pos = atomicAdd(&g_cur[d], 1);
    g_edge[pos] = make_int2(s, __float_as_int(expf(-edt[e])));
}

// ---------------- K5: per-dst score + top-16 + softmax + gather --------------
// Both gathers fp16 (Kh, Xh): 256B/row; fp32 accumulation throughout.
__global__ void __launch_bounds__(256) attn_kernel(int n) {
    int warp = (blockIdx.x * blockDim.x + threadIdx.x) >> 5;
    int lane = threadIdx.x & 31;
    if (warp >= n) return;
    int d = warp;
    int deg = g_deg[d];
    if (deg == 0) {
        ((float4*)g_H)[(size_t)d * 32 + lane] = make_float4(0.f, 0.f, 0.f, 0.f);
        return;
    }
    int off = g_off[d];
    const float4* Qv4 = (const float4*)g_Qv;
    float4 q = Qv4[(size_t)d * 32 + lane];   // Qv[d], dims [4*lane, 4*lane+4)

    float s0 = -INFINITY, s1 = -INFINITY, s2 = -INFINITY, s3 = -INFINITY;
    int r0 = -1, r1 = -1, r2 = -1, r3 = -1;

    int jmax = deg < 128 ? deg : 128;
    for (int j = 0; j < jmax; j++) {
        int2 ed = g_edge[off + j];
        int src = ed.x;
        uint2 kv = ((const uint2*)(g_Kh + (size_t)src * DIMD))[lane];  // 4 fp16
        float2 f0 = __half22float2(*(__half2*)&kv.x);
        float2 f1 = __half22float2(*(__half2*)&kv.y);
        float p = q.x * f0.x + q.y * f0.y + q.z * f1.x + q.w * f1.y;
        #pragma unroll
        for (int o = 16; o; o >>= 1) p += __shfl_xor_sync(0xffffffffu, p, o);
        float sc = p * INV_SQRT_D * __int_as_float(ed.y);
        if ((j & 31) == lane) {
            int sl = j >> 5;
            if (sl == 0) { s0 = sc; r0 = src; }
            else if (sl == 1) { s1 = sc; r1 = src; }
            else if (sl == 2) { s2 = sc; r2 = src; }
            else             { s3 = sc; r3 = src; }
        }
    }
    for (int j = 128; j < deg; j++) {
        int2 ed = g_edge[off + j];
        int src = ed.x;
        uint2 kv = ((const uint2*)(g_Kh + (size_t)src * DIMD))[lane];
        float2 f0 = __half22float2(*(__half2*)&kv.x);
        float2 f1 = __half22float2(*(__half2*)&kv.y);
        float p = q.x * f0.x + q.y * f0.y + q.z * f1.x + q.w * f1.y;
        #pragma unroll
        for (int o = 16; o; o >>= 1) p += __shfl_xor_sync(0xffffffffu, p, o);
        float sc = p * INV_SQRT_D * __int_as_float(ed.y);
        float mv = s0; int msl = 0;
        if (s1 < mv) { mv = s1; msl = 1; }
        if (s2 < mv) { mv = s2; msl = 2; }
        if (s3 < mv) { mv = s3; msl = 3; }
        float bv = mv; int bl = lane;
        #pragma unroll
        for (int o = 16; o; o >>= 1) {
            float ov = __shfl_xor_sync(0xffffffffu, bv, o);
            int   ol = __shfl_xor_sync(0xffffffffu, bl, o);
            if (ov < bv || (ov == bv && ol < bl)) { bv = ov; bl = ol; }
        }
        if (sc > bv && lane == bl) {
            if (msl == 0) { s0 = sc; r0 = src; }
            else if (msl == 1) { s1 = sc; r1 = src; }
            else if (msl == 2) { s2 = sc; r2 = src; }
            else              { s3 = sc; r3 = src; }
        }
    }

    int K = deg < TOPK ? deg : TOPK;
    float sel_v; int sel_src;
    if (deg <= TOPK) {
        sel_v = s0; sel_src = r0;
    } else {
        sel_v = -INFINITY; sel_src = -1;
        for (int it = 0; it < TOPK; it++) {
            float v = s0; int sl = 0;
            if (s1 > v) { v = s1; sl = 1; }
            if (s2 > v) { v = s2; sl = 2; }
            if (s3 > v) { v = s3; sl = 3; }
            float bv = v; int bl = lane;
            #pragma unroll
            for (int o = 16; o; o >>= 1) {
                float ov = __shfl_xor_sync(0xffffffffu, bv, o);
                int   ol = __shfl_xor_sync(0xffffffffu, bl, o);
                if (ov > bv || (ov == bv && ol < bl)) { bv = ov; bl = ol; }
            }
            int bslot = __shfl_sync(0xffffffffu, sl, bl);
            int csrc = (bslot == 0) ? r0 : (bslot == 1) ? r1 : (bslot == 2) ? r2 : r3;
            int bsrc = __shfl_sync(0xffffffffu, csrc, bl);
            if (lane == bl) {
                if (bslot == 0) s0 = -INFINITY;
                else if (bslot == 1) s1 = -INFINITY;
                else if (bslot == 2) s2 = -INFINITY;
                else                 s3 = -INFINITY;
            }
            if (lane == it) { sel_v = bv; sel_src = bsrc; }
        }
    }

    float mred = (sel_src >= 0) ? sel_v : -INFINITY;
    #pragma unroll
    for (int o = 16; o; o >>= 1) mred = fmaxf(mred, __shfl_xor_sync(0xffffffffu, mred, o));
    float w = (sel_src >= 0) ? expf(sel_v - mred) : 0.f;
    float wsum = w;
    #pragma unroll
    for (int o = 16; o; o >>= 1) wsum += __shfl_xor_sync(0xffffffffu, wsum, o);
    float alpha = w / wsum;

    float4 acc = make_float4(0.f, 0.f, 0.f, 0.f);
    for (int k2 = 0; k2 < K; k2++) {
        float a = __shfl_sync(0xffffffffu, alpha, k2);
        int  sr = __shfl_sync(0xffffffffu, sel_src, k2);
        uint2 xv = ((const uint2*)(g_Xh + (size_t)sr * DIMD))[lane];
        float2 x0 = __half22float2(*(__half2*)&xv.x);
        float2 x1 = __half22float2(*(__half2*)&xv.y);
        acc.x += a * x0.x; acc.y += a * x0.y; acc.z += a * x1.x; acc.w += a * x1.y;
    }
    ((float4*)g_H)[(size_t)d * 32 + lane] = acc;
}

// ---------------- bf16 mma.sync helper ----------------
__device__ __forceinline__ void mma_bf16(float* c, const uint32_t* a, const uint32_t* b) {
    asm volatile(
        "mma.sync.aligned.m16n8k16.row.col.f32.bf16.bf16.f32 "
        "{%0,%1,%2,%3}, {%4,%5,%6,%7}, {%8,%9}, {%0,%1,%2,%3};"
        : "+f"(c[0]), "+f"(c[1]), "+f"(c[2]), "+f"(c[3])
        : "r"(a[0]), "r"(a[1]), "r"(a[2]), "r"(a[3]), "r"(b[0]), "r"(b[1]));
}

// ---------------- K1: fused QK GEMM — X loaded ONCE, two outputs ------------
// 512 threads: sub-block 0 (warps 0-7) -> Qv = X*Wq^T (fp32)
//              sub-block 1 (warps 8-15) -> Kh = X*Wk^T (fp16)
// Shared A (X) SMEM tiles; per-sub B tiles. 2 K-chunks of 64.
__global__ void __launch_bounds__(512, 1) gemm0_fused(const float* __restrict__ X, int n) {
    extern __shared__ __nv_bfloat16 sm[];
    __nv_bfloat16* Ahi = sm;                          // 128*BST
    __nv_bfloat16* Alo = sm + 128 * BST;
    int tid = threadIdx.x;
    int sub = tid >> 8;            // 0 -> Wq/Qv, 1 -> Wk/Kh
    int t8 = tid & 255;
    int lane = tid & 31;
    int warp8 = t8 >> 5;
    int wm = warp8 >> 1;
    int wn = warp8 & 1;
    int gr = lane >> 2;
    int gc = lane & 3;
    int rowBase = blockIdx.x * 128;
    __nv_bfloat16* Bhi = sm + (2 + 2 * sub) * 128 * BST;
    __nv_bfloat16* Blo = Bhi + 128 * BST;

    float acc[2][8][4];
    #pragma unroll
    for (int mi = 0; mi < 2; mi++)
        #pragma unroll
        for (int ni = 0; ni < 8; ni++)
            #pragma unroll
            for (int q = 0; q < 4; q++) acc[mi][ni][q] = 0.f;

    for (int ch = 0; ch < 2; ch++) {
        int koff = ch * 64;
        // ---- A-fill by all 512 threads (4096 float2 pairs) ----
        #pragma unroll
        for (int p = 0; p < 8; p++) {
            int f = tid + p * 512;
            int row = f >> 5;
            int kk = (f & 31) * 2;
            int g = kk >> 4, j = kk & 15;
            int pos = row * BST + g * 16 + pair_pos(j);
            int grow = rowBase + row;
            float2 v = make_float2(0.f, 0.f);
            if (grow < n) v = *(const float2*)&X[(size_t)grow * DIMD + koff + kk];
            __nv_bfloat16 h0 = __float2bfloat16(v.x);
            __nv_bfloat16 h1 = __float2bfloat16(v.y);
            __nv_bfloat16 l0 = __float2bfloat16(v.x - __bfloat162float(h0));
            __nv_bfloat16 l1 = __float2bfloat16(v.y - __bfloat162float(h1));
            *(__nv_bfloat162*)&Ahi[pos] = __nv_bfloat162(h0, h1);
            *(__nv_bfloat162*)&Alo[pos] = __nv_bfloat162(l0, l1);
        }
        // ---- B-fill: each sub-block copies its own weight image ----
        {
            int wsel = 2 + sub;
            const uint4* sh = (const uint4*)&g_Wsplit[wsel][0][ch][0];
            const uint4* sl = (const uint4*)&g_Wsplit[wsel][1][ch][0];
            uint4* dh = (uint4*)Bhi;
            uint4* dl = (uint4*)Blo;
            #pragma unroll
            for (int p = 0; p < 5; p++) {     // 1280 uint4 per buffer
                int f = t8 + p * 256;
                dh[f] = sh[f];
                dl[f] = sl[f];
            }
        }
        __syncthreads();

        #pragma unroll
        for (int g = 0; g < 4; g++) {
            uint32_t ahi[2][4], alo[2][4];
            #pragma unroll
            for (int mi = 0; mi < 2; mi++) {
                int r0 = wm * 32 + mi * 16 + gr;
                uint2 h0 = *(const uint2*)&Ahi[r0 * BST + g * 16 + gc * 4];
                uint2 h1 = *(const uint2*)&Ahi[(r0 + 8) * BST + g * 16 + gc * 4];
                ahi[mi][0] = h0.x; ahi[mi][2] = h0.y;
                ahi[mi][1] = h1.x; ahi[mi][3] = h1.y;
                uint2 l0 = *(const uint2*)&Alo[r0 * BST + g * 16 + gc * 4];
                uint2 l1 = *(const uint2*)&Alo[(r0 + 8) * BST + g * 16 + gc * 4];
                alo[mi][0] = l0.x; alo[mi][2] = l0.y;
                alo[mi][1] = l1.x; alo[mi][3] = l1.y;
            }
            #pragma unroll
            for (int ni = 0; ni < 8; ni++) {
                int nr = wn * 64 + ni * 8 + gr;
                uint2 bh = *(const uint2*)&Bhi[nr * BST + g * 16 + gc * 4];
                uint2 bl = *(const uint2*)&Blo[nr * BST + g * 16 + gc * 4];
                uint32_t bhv[2] = { bh.x, bh.y };
                uint32_t blv[2] = { bl.x, bl.y };
                mma_bf16(acc[0][ni], ahi[0], bhv);
                mma_bf16(acc[1][ni], ahi[1], bhv);
                mma_bf16(acc[0][ni], ahi[0], blv);
                mma_bf16(acc[1][ni], ahi[1], blv);
                mma_bf16(acc[0][ni], alo[0], bhv);
                mma_bf16(acc[1][ni], alo[1], bhv);
            }
        }
        __syncthreads();
    }

    #pragma unroll
    for (int mi = 0; mi < 2; mi++) {
        #pragma unroll
        for (int ni = 0; ni < 8; ni++) {
            int gcol = wn * 64 + ni * 8 + 2 * gc;
            int grow0 = rowBase + wm * 32 + mi * 16 + gr;
            float v0 = acc[mi][ni][0], v1 = acc[mi][ni][1];
            float v2 = acc[mi][ni][2], v3 = acc[mi][ni][3];
            if (sub == 1) {
                if (grow0 < n)
                    *(__half2*)&g_Kh[(size_t)grow0 * DIMD + gcol] = __floats2half2_rn(v0, v1);
                if (grow0 + 8 < n)
                    *(__half2*)&g_Kh[(size_t)(grow0 + 8) * DIMD + gcol] = __floats2half2_rn(v2, v3);
            } else {
                if (grow0 < n)     *(float2*)&g_Qv[(size_t)grow0 * DIMD + gcol]       = make_float2(v0, v1);
                if (grow0 + 8 < n) *(float2*)&g_Qv[(size_t)(grow0 + 8) * DIMD + gcol] = make_float2(v2, v3);
            }
        }
    }
}

// ---------------- K6: epilogue GEMM out = relu(X*Wself^T + H*Wmsg^T) --------
__global__ void __launch_bounds__(256, 2) mma_gemm1(const float* __restrict__ X,
                                                    float* __restrict__ Cext, int n) {
    extern __shared__ __nv_bfloat16 sm[];
    __nv_bfloat16* Ahi = sm;
    __nv_bfloat16* Alo = sm + 128 * BST;
    __nv_bfloat16* Bhi = sm + 2 * 128 * BST;
    __nv_bfloat16* Blo = sm + 3 * 128 * BST;

    int tid = threadIdx.x;
    int lane = tid & 31;
    int warp = tid >> 5;
    int wm = warp >> 1;
    int wn = warp & 1;
    int gr = lane >> 2;
    int gc = lane & 3;
    int rowBase = blockIdx.y * 128;

    float acc[2][8][4];
    #pragma unroll
    for (int mi = 0; mi < 2; mi++)
        #pragma unroll
        for (int ni = 0; ni < 8; ni++)
            #pragma unroll
            for (int q = 0; q < 4; q++) acc[mi][ni][q] = 0.f;

    for (int ch = 0; ch < 4; ch++) {
        const float* Asrc = (ch < 2) ? X : g_H;
        int koff = (ch < 2 ? ch : ch - 2) * 64;
        int wsel = (ch < 2) ? 0 : 1;
        int wch = (ch < 2) ? ch : ch - 2;

        #pragma unroll
        for (int p = 0; p < 16; p++) {
            int f = tid + p * 256;
            int row = f >> 5;
            int kk = (f & 31) * 2;
            int g = kk >> 4, j = kk & 15;
            int pos = row * BST + g * 16 + pair_pos(j);
            int grow = rowBase + row;
            float2 v = make_float2(0.f, 0.f);
            if (grow < n) v = *(const float2*)&Asrc[(size_t)grow * DIMD + koff + kk];
            __nv_bfloat16 h0 = __float2bfloat16(v.x);
            __nv_bfloat16 h1 = __float2bfloat16(v.y);
            __nv_bfloat16 l0 = __float2bfloat16(v.x - __bfloat162float(h0));
            __nv_bfloat16 l1 = __float2bfloat16(v.y - __bfloat162float(h1));
            *(__nv_bfloat162*)&Ahi[pos] = __nv_bfloat162(h0, h1);
            *(__nv_bfloat162*)&Alo[pos] = __nv_bfloat162(l0, l1);
        }
        {
            const uint4* sh = (const uint4*)&g_Wsplit[wsel][0][wch][0];
            const uint4* sl = (const uint4*)&g_Wsplit[wsel][1][wch][0];
            uint4* dh = (uint4*)Bhi;
            uint4* dl = (uint4*)Blo;
            #pragma unroll
            for (int p = 0; p < 5; p++) {
                int f = tid + p * 256;
                dh[f] = sh[f];
                dl[f] = sl[f];
            }
        }
        __syncthreads();

        #pragma unroll
        for (int g = 0; g < 4; g++) {
            uint32_t ahi[2][4], alo[2][4];
            #pragma unroll
            for (int mi = 0; mi < 2; mi++) {
                int r0 = wm * 32 + mi * 16 + gr;
                uint2 h0 = *(const uint2*)&Ahi[r0 * BST + g * 16 + gc * 4];
                uint2 h1 = *(const uint2*)&Ahi[(r0 + 8) * BST + g * 16 + gc * 4];
                ahi[mi][0] = h0.x; ahi[mi][2] = h0.y;
                ahi[mi][1] = h1.x; ahi[mi][3] = h1.y;
                uint2 l0 = *(const uint2*)&Alo[r0 * BST + g * 16 + gc * 4];
                uint2 l1 = *(const uint2*)&Alo[(r0 + 8) * BST + g * 16 + gc * 4];
                alo[mi][0] = l0.x; alo[mi][2] = l0.y;
                alo[mi][1] = l1.x; alo[mi][3] = l1.y;
            }
            #pragma unroll
            for (int ni = 0; ni < 8; ni++) {
                int nr = wn * 64 + ni * 8 + gr;
                uint2 bh = *(const uint2*)&Bhi[nr * BST + g * 16 + gc * 4];
                uint2 bl = *(const uint2*)&Blo[nr * BST + g * 16 + gc * 4];
                uint32_t bhv[2] = { bh.x, bh.y };
                uint32_t blv[2] = { bl.x, bl.y };
                mma_bf16(acc[0][ni], ahi[0], bhv);
                mma_bf16(acc[1][ni], ahi[1], bhv);
                mma_bf16(acc[0][ni], ahi[0], blv);
                mma_bf16(acc[1][ni], ahi[1], blv);
                mma_bf16(acc[0][ni], alo[0], bhv);
                mma_bf16(acc[1][ni], alo[1], bhv);
            }
        }
        __syncthreads();
    }

    #pragma unroll
    for (int mi = 0; mi < 2; mi++) {
        #pragma unroll
        for (int ni = 0; ni < 8; ni++) {
            int gcol = wn * 64 + ni * 8 + 2 * gc;
            int grow0 = rowBase + wm * 32 + mi * 16 + gr;
            float v0 = fmaxf(acc[mi][ni][0], 0.f), v1 = fmaxf(acc[mi][ni][1], 0.f);
            float v2 = fmaxf(acc[mi][ni][2], 0.f), v3 = fmaxf(acc[mi][ni][3], 0.f);
            if (grow0 < n)     *(float2*)&Cext[(size_t)grow0 * DIMD + gcol]       = make_float2(v0, v1);
            if (grow0 + 8 < n) *(float2*)&Cext[(size_t)(grow0 + 8) * DIMD + gcol] = make_float2(v2, v3);
        }
    }
}

#define GEMM_SMEM  (4 * 128 * BST * 2)
#define GEMM0_SMEM (6 * 128 * BST * 2)

// ---------------- entry (serial chain — proven fastest ordering) ------------
extern "C" void kernel_launch(void* const* d_in, const int* in_sizes, int n_in,
                              void* d_out, int out_size) {
    const float* X     = (const float*)d_in[0];
    const void*  eidx  = d_in[1];
    const float* edt   = (const float*)d_in[2];
    const float* Wself = (const float*)d_in[3];
    const float* Wmsg  = (const float*)d_in[4];
    const float* Wq    = (const float*)d_in[5];
    const float* Wk    = (const float*)d_in[6];
    float* out = (float*)d_out;

    int n = in_sizes[0] / DIMD;
    int m = in_sizes[2];
    int rowTiles = (n + 127) / 128;

    cudaFuncSetAttribute(gemm0_fused, cudaFuncAttributeMaxDynamicSharedMemorySize, GEMM0_SMEM);
    cudaFuncSetAttribute(mma_gemm1, cudaFuncAttributeMaxDynamicSharedMemorySize, GEMM_SMEM);

    prep_kernel<<<(n + 255) / 256, 256>>>(X, eidx, Wself, Wmsg, Wq, Wk, n);
    gemm0_fused<<<rowTiles, 512, GEMM0_SMEM>>>(X, n);
    hist_kernel<<<(m + 255) / 256, 256>>>(eidx, m);
    offsets_kernel<<<(n + 255) / 256, 256>>>(n);
    scatter_kernel<<<(m + 255) / 256, 256>>>(eidx, edt, m);
    attn_kernel<<<(n + 7) / 8, 256>>>(n);
    mma_gemm1<<<dim3(1, rowTiles), 256, GEMM_SMEM>>>(X, out, n);
}